// round 2
// baseline (speedup 1.0000x reference)
#include <cuda_runtime.h>
#include <cuda_bf16.h>

#define DIM 128
#define TEMP_INV (1.0f / 0.07f)

// Flag set by the detection kernel: 1 if index buffers are int64, 0 if int32.
__device__ int g_idx_is64;

// Index values are uniform in [0, 1e6) -> fit in 20 bits. If stored as
// little-endian int64, every odd 32-bit word is zero. If int32, odd words are
// random indices; P(64 all zero) ~ 0.
__global__ void detect_idx_kernel(const unsigned int* __restrict__ idx_words) {
    if (threadIdx.x == 0) {
        unsigned int acc = 0;
#pragma unroll
        for (int i = 1; i < 128; i += 2) acc |= idx_words[i];
        g_idx_is64 = (acc == 0) ? 1 : 0;
    }
}

__device__ __forceinline__ float dot4(float4 a, float4 b) {
    return a.x * b.x + a.y * b.y + a.z * b.z + a.w * b.w;
}

__global__ __launch_bounds__(256, 4)
void la_loss_kernel(const float* __restrict__ codes,
                    const float* __restrict__ bank,
                    const void* __restrict__ idx_bg,
                    const void* __restrict__ idx_cl,
                    float* __restrict__ out,
                    int K)
{
    const int b    = blockIdx.x;
    const int tid  = threadIdx.x;
    const int wid  = tid >> 5;      // 0..7
    const int lane = tid & 31;
    const bool is64 = (g_idx_is64 != 0);

    // ---- load this batch row's code vector and normalize (per-warp) ----
    float4 c4 = reinterpret_cast<const float4*>(codes + (size_t)b * DIM)[lane];
    float ss = dot4(c4, c4);
#pragma unroll
    for (int o = 16; o; o >>= 1) ss += __shfl_xor_sync(0xffffffffu, ss, o);
    const float rn = rsqrtf(ss);
    const float4 v4 = make_float4(c4.x * rn, c4.y * rn, c4.z * rn, c4.w * rn);

    // warps 0-3 -> background indices, warps 4-7 -> close indices
    const void* idx = (wid < 4) ? idx_bg : idx_cl;
    const int wsub = wid & 3;
    const size_t base = (size_t)b * (size_t)K;
    const float4* __restrict__ bank4 = reinterpret_cast<const float4*>(bank);

    float acc = 0.0f;
    int n = wsub;

    // main loop: 4 rows per iteration, loads batched up front, reductions interleaved
    for (; n + 12 < K; n += 16) {
        long long i0, i1, i2, i3;
        if (is64) {
            const long long* p = reinterpret_cast<const long long*>(idx) + base;
            i0 = p[n]; i1 = p[n + 4]; i2 = p[n + 8]; i3 = p[n + 12];
        } else {
            const int* p = reinterpret_cast<const int*>(idx) + base;
            i0 = p[n]; i1 = p[n + 4]; i2 = p[n + 8]; i3 = p[n + 12];
        }
        // 4 independent 512B coalesced row loads in flight
        float4 r0 = bank4[(size_t)i0 * 32 + lane];
        float4 r1 = bank4[(size_t)i1 * 32 + lane];
        float4 r2 = bank4[(size_t)i2 * 32 + lane];
        float4 r3 = bank4[(size_t)i3 * 32 + lane];

        float d0 = dot4(r0, v4);
        float d1 = dot4(r1, v4);
        float d2 = dot4(r2, v4);
        float d3 = dot4(r3, v4);

        // 4 independent butterfly chains -> SHFL latency overlaps
#pragma unroll
        for (int o = 16; o; o >>= 1) {
            d0 += __shfl_xor_sync(0xffffffffu, d0, o);
            d1 += __shfl_xor_sync(0xffffffffu, d1, o);
            d2 += __shfl_xor_sync(0xffffffffu, d2, o);
            d3 += __shfl_xor_sync(0xffffffffu, d3, o);
        }
        acc += __expf(d0 * TEMP_INV) + __expf(d1 * TEMP_INV)
             + __expf(d2 * TEMP_INV) + __expf(d3 * TEMP_INV);
    }

    // remainder (K=200, stride 4 -> 50 rows/warp -> 2 leftover)
    for (; n < K; n += 4) {
        long long ii;
        if (is64) ii = reinterpret_cast<const long long*>(idx)[base + n];
        else      ii = (long long)reinterpret_cast<const int*>(idx)[base + n];
        float4 r = bank4[(size_t)ii * 32 + lane];
        float d = dot4(r, v4);
#pragma unroll
        for (int o = 16; o; o >>= 1) d += __shfl_xor_sync(0xffffffffu, d, o);
        acc += __expf(d * TEMP_INV);
    }

    __shared__ float s[8];
    if (lane == 0) s[wid] = acc;
    __syncthreads();
    if (tid == 0) {
        float d1 = s[0] + s[1] + s[2] + s[3];
        float d2 = s[4] + s[5] + s[6] + s[7];
        out[b] = logf(d1) - logf(d2);
    }
}

extern "C" void kernel_launch(void* const* d_in, const int* in_sizes, int n_in,
                              void* d_out, int out_size) {
    const float* codes = (const float*)d_in[0];
    const float* bank  = (const float*)d_in[1];
    const void*  ibg   = d_in[2];
    const void*  icl   = d_in[3];
    float* out = (float*)d_out;

    const int B = out_size;                 // 1024
    const int K = in_sizes[2] / B;          // 200

    detect_idx_kernel<<<1, 32>>>((const unsigned int*)ibg);
    la_loss_kernel<<<B, 256>>>(codes, bank, ibg, icl, out, K);
}